// round 3
// baseline (speedup 1.0000x reference)
#include <cuda_runtime.h>
#include <cstdint>

// ---------------------------------------------------------------------------
// GRU decoder rollout, fused fc_in, persistent-per-thread hidden state.
// Row r = b*C + c owns its full 48-step recurrence (rows independent).
// h lives in registers as 32 packed f32x2 pairs; W_hh lives in SMEM pre-packed
// as ulonglong2 so fma.rn.f32x2 consumes LDS.128 results directly.
// ---------------------------------------------------------------------------

#define B_      64
#define T_HIST  24
#define T_FC    48
#define C_      4096
#define F_IN    8
#define HID     64
#define NROWS   (B_ * C_)          // 262144
#define TPB     128
#define NBLK    (NROWS / TPB)      // 2048

typedef unsigned long long ull;

// scratch: addressable h copy, [k][row] layout for coalescing. 64 MB, L2-resident.
__device__ float g_hbuf[HID * NROWS];

__device__ __forceinline__ ull fma2(ull a, ull b, ull c) {
    ull d;
    asm("fma.rn.f32x2 %0, %1, %2, %3;" : "=l"(d) : "l"(a), "l"(b), "l"(c));
    return d;
}
__device__ __forceinline__ ull pack2(float a, float b) {
    ull v;
    asm("mov.b64 %0, {%1, %2};" : "=l"(v) : "f"(a), "f"(b));
    return v;
}
__device__ __forceinline__ float2 unpack2(ull v) {
    float2 r;
    asm("mov.b64 {%0, %1}, %2;" : "=f"(r.x), "=f"(r.y) : "l"(v));
    return r;
}
__device__ __forceinline__ float sigm(float x) {
    return __fdividef(1.0f, 1.0f + __expf(-x));
}
__device__ __forceinline__ float tanh_(float x) {
    return 1.0f - 2.0f * __fdividef(1.0f, 1.0f + __expf(2.0f * x));
}

// SMEM layout (bytes):
//  WRZ : 64u * 32kp * ulonglong2 (Wr pair, Wz pair)            = 32768
//  WN  : 64u * 16kq * ulonglong2 (Wn pairs 2kq, 2kq+1)         = 16384
//  GIA/GIB/GIC : 3 * 64 * float4 {F1,F2,F3, bias}              =  3072
//  F0  : 64 * float4 {Fr0, Fz0, Fn0, b_hh_n}                   =  1024
//  WO  : 64 floats                                              =   256
#define SMEM_BYTES (32768 + 16384 + 3072 + 1024 + 256)

__global__ void __launch_bounds__(TPB, 3)
decoder_kernel(const float* __restrict__ X,
               const float* __restrict__ H,
               const float* __restrict__ xn,
               const float* __restrict__ W_in,
               const float* __restrict__ b_in,
               const float* __restrict__ W_ih,
               const float* __restrict__ W_hh,
               const float* __restrict__ b_ih,
               const float* __restrict__ b_hh,
               const float* __restrict__ W_out,
               const float* __restrict__ b_out,
               float* __restrict__ out)
{
    extern __shared__ __align__(16) unsigned char smem_raw[];
    ulonglong2* const WRZ = (ulonglong2*)smem_raw;
    ulonglong2* const WN  = WRZ + 64 * 32;
    float4* const GIA = (float4*)(WN + 64 * 16);
    float4* const GIB = GIA + 64;
    float4* const GIC = GIB + 64;
    float*  const F0f = (float*)(GIC + 64);               // 256 floats
    float*  const WO  = F0f + 256;

    const int tid = threadIdx.x;

    // ---- setup phase: pack W_hh, build fused input weights ----
    for (int e = tid; e < 64 * 32; e += TPB) {
        int u = e >> 5, kp = e & 31;
        float a0 = W_hh[u * 64 + 2 * kp];
        float a1 = W_hh[u * 64 + 2 * kp + 1];
        float b0 = W_hh[(64 + u) * 64 + 2 * kp];
        float b1 = W_hh[(64 + u) * 64 + 2 * kp + 1];
        ulonglong2 v; v.x = pack2(a0, a1); v.y = pack2(b0, b1);
        WRZ[e] = v;
    }
    for (int e = tid; e < 64 * 16; e += TPB) {
        int u = e >> 4, kq = e & 15;
        const float* wn = W_hh + (128 + u) * 64 + 4 * kq;
        ulonglong2 v; v.x = pack2(wn[0], wn[1]); v.y = pack2(wn[2], wn[3]);
        WN[e] = v;
    }
    for (int j = tid; j < 192; j += TPB) {
        // F[j][0..3] = W_ih[j] . W_in[:,c] ;  bF = W_ih[j] . b_in + b_ih[j]
        float f0 = 0.f, f1 = 0.f, f2 = 0.f, f3 = 0.f, fb = 0.f;
        const float* wih = W_ih + j * 64;
        #pragma unroll 8
        for (int k = 0; k < 64; k++) {
            float w = wih[k];
            f0 = fmaf(w, W_in[k * 4 + 0], f0);
            f1 = fmaf(w, W_in[k * 4 + 1], f1);
            f2 = fmaf(w, W_in[k * 4 + 2], f2);
            f3 = fmaf(w, W_in[k * 4 + 3], f3);
            fb = fmaf(w, b_in[k], fb);
        }
        fb += b_ih[j];
        int gate = j >> 6, u = j & 63;
        if (gate == 0) {
            GIA[u] = make_float4(f1, f2, f3, fb + b_hh[j]);
            F0f[4 * u + 0] = f0;
        } else if (gate == 1) {
            GIB[u] = make_float4(f1, f2, f3, fb + b_hh[j]);
            F0f[4 * u + 1] = f0;
        } else {
            GIC[u] = make_float4(f1, f2, f3, fb);   // b_hh_n applied on the dn side
            F0f[4 * u + 2] = f0;
            F0f[4 * u + 3] = b_hh[j];
        }
    }
    if (tid < 64) WO[tid] = W_out[tid];
    __syncthreads();

    // ---- per-thread recurrence ----
    const int r = blockIdx.x * TPB + tid;
    const int b = r >> 12;           // / C_
    const int c = r & (C_ - 1);

    ull h2[32];
    {
        const float* Hrow = H + (size_t)r * HID;
        #pragma unroll
        for (int i = 0; i < 16; i++) {
            float4 v = *(const float4*)(Hrow + 4 * i);
            h2[2 * i]     = pack2(v.x, v.y);
            h2[2 * i + 1] = pack2(v.z, v.w);
            g_hbuf[(4 * i + 0) * NROWS + r] = v.x;
            g_hbuf[(4 * i + 1) * NROWS + r] = v.y;
            g_hbuf[(4 * i + 2) * NROWS + r] = v.z;
            g_hbuf[(4 * i + 3) * NROWS + r] = v.w;
        }
    }
    float xprev = xn[r];
    const float bout = b_out[0];
    const float* Xb = X + (((size_t)(b * (T_HIST + T_FC) + T_HIST)) * C_ + c) * F_IN + 4;
    float* outb = out + (size_t)b * T_FC * C_ + c;

    #pragma unroll 1
    for (int t = 0; t < T_FC; t++) {
        float4 xf = *(const float4*)(Xb + (size_t)t * C_ * F_IN);
        const float x0 = xf.y, x1 = xf.z, x2 = xf.w;   // features 5,6,7
        float xacc = 0.f;

        #pragma unroll 2
        for (int u = 0; u < 64; u++) {
            ull ar = 0ull, az = 0ull, an = 0ull;
            const ulonglong2* wrz = WRZ + (u << 5);
            const ulonglong2* wn  = WN + (u << 4);
            #pragma unroll
            for (int kq = 0; kq < 16; kq++) {
                ulonglong2 w0  = wrz[2 * kq];
                ulonglong2 w1  = wrz[2 * kq + 1];
                ulonglong2 wnn = wn[kq];
                ar = fma2(w0.x,  h2[2 * kq],     ar);
                az = fma2(w0.y,  h2[2 * kq],     az);
                an = fma2(wnn.x, h2[2 * kq],     an);
                ar = fma2(w1.x,  h2[2 * kq + 1], ar);
                az = fma2(w1.y,  h2[2 * kq + 1], az);
                an = fma2(wnn.y, h2[2 * kq + 1], an);
            }
            float2 fr = unpack2(ar), fz = unpack2(az), fn = unpack2(an);
            float dr = fr.x + fr.y, dz = fz.x + fz.y, dn = fn.x + fn.y;

            float4 ga = GIA[u], gb = GIB[u], gc = GIC[u];
            float4 f0 = ((const float4*)F0f)[u];
            float gir = fmaf(ga.x, x0, fmaf(ga.y, x1, fmaf(ga.z, x2, fmaf(f0.x, xprev, ga.w))));
            float giz = fmaf(gb.x, x0, fmaf(gb.y, x1, fmaf(gb.z, x2, fmaf(f0.y, xprev, gb.w))));
            float gin = fmaf(gc.x, x0, fmaf(gc.y, x1, fmaf(gc.z, x2, fmaf(f0.z, xprev, gc.w))));

            float rg = sigm(gir + dr);
            float zg = sigm(giz + dz);
            float ng = tanh_(fmaf(rg, dn + f0.w, gin));

            float hu = g_hbuf[u * NROWS + r];          // h_old[u] (runtime index)
            float hn = ng + zg * (hu - ng);            // (1-z)*n + z*h
            g_hbuf[u * NROWS + r] = hn;                // safe in-place: dots use h2 regs
            xacc = fmaf(WO[u], hn, xacc);
        }

        float xo = xacc + bout;
        outb[(size_t)t * C_] = xo;
        xprev = xo;

        // refresh register copy of h from scratch (L2-hit reads, constant indices)
        #pragma unroll
        for (int i = 0; i < 16; i++) {
            float a0 = g_hbuf[(4 * i + 0) * NROWS + r];
            float a1 = g_hbuf[(4 * i + 1) * NROWS + r];
            float a2 = g_hbuf[(4 * i + 2) * NROWS + r];
            float a3 = g_hbuf[(4 * i + 3) * NROWS + r];
            h2[2 * i]     = pack2(a0, a1);
            h2[2 * i + 1] = pack2(a2, a3);
        }
    }
}

extern "C" void kernel_launch(void* const* d_in, const int* in_sizes, int n_in,
                              void* d_out, int out_size)
{
    const float* X    = (const float*)d_in[0];
    const float* H    = (const float*)d_in[1];
    const float* xn   = (const float*)d_in[2];
    const float* W_in = (const float*)d_in[3];
    const float* b_in = (const float*)d_in[4];
    const float* W_ih = (const float*)d_in[5];
    const float* W_hh = (const float*)d_in[6];
    const float* b_ih = (const float*)d_in[7];
    const float* b_hh = (const float*)d_in[8];
    const float* W_out= (const float*)d_in[9];
    const float* b_out= (const float*)d_in[10];
    float* out = (float*)d_out;

    cudaFuncSetAttribute(decoder_kernel,
                         cudaFuncAttributeMaxDynamicSharedMemorySize, SMEM_BYTES);
    decoder_kernel<<<NBLK, TPB, SMEM_BYTES>>>(X, H, xn, W_in, b_in, W_ih, W_hh,
                                              b_ih, b_hh, W_out, b_out, out);
}

// round 5
// speedup vs baseline: 1.2833x; 1.2833x over previous
#include <cuda_runtime.h>
#include <cstdint>

// ---------------------------------------------------------------------------
// GRU decoder rollout, fused fc_in, persistent hidden state, R=2 rows/thread.
// Weights (W_hh packed as ulonglong2) are read once per u-iteration and applied
// to BOTH rows -> halves the SMEM wavefront traffic per row (L1 was 94.5%).
// ---------------------------------------------------------------------------

#define B_      64
#define T_HIST  24
#define T_FC    48
#define C_      4096
#define F_IN    8
#define HID     64
#define NROWS   (B_ * C_)          // 262144
#define TPB     128
#define ROWS_PB (2 * TPB)          // 256 rows per block
#define NBLK    (NROWS / ROWS_PB)  // 1024

typedef unsigned long long ull;

// scratch: addressable h copy, [k][row] layout for coalescing. 64 MB, L2-resident.
__device__ float g_hbuf[HID * NROWS];

__device__ __forceinline__ ull fma2(ull a, ull b, ull c) {
    ull d;
    asm("fma.rn.f32x2 %0, %1, %2, %3;" : "=l"(d) : "l"(a), "l"(b), "l"(c));
    return d;
}
__device__ __forceinline__ ull pack2(float a, float b) {
    ull v;
    asm("mov.b64 %0, {%1, %2};" : "=l"(v) : "f"(a), "f"(b));
    return v;
}
__device__ __forceinline__ float2 unpack2(ull v) {
    float2 r;
    asm("mov.b64 {%0, %1}, %2;" : "=f"(r.x), "=f"(r.y) : "l"(v));
    return r;
}
__device__ __forceinline__ float sigm(float x) {
    return __fdividef(1.0f, 1.0f + __expf(-x));
}
__device__ __forceinline__ float tanh_(float x) {
    return 1.0f - 2.0f * __fdividef(1.0f, 1.0f + __expf(2.0f * x));
}

// SMEM layout (bytes):
//  WRZ : 64u * 32kp * ulonglong2 (Wr pair, Wz pair)            = 32768
//  WN  : 64u * 16kq * ulonglong2 (Wn pairs 2kq, 2kq+1)         = 16384
//  GIA/GIB/GIC : 3 * 64 * float4 {F1,F2,F3, bias}              =  3072
//  F0  : 64 * float4 {Fr0, Fz0, Fn0, b_hh_n}                   =  1024
//  WO  : 64 floats                                              =   256
#define SMEM_BYTES (32768 + 16384 + 3072 + 1024 + 256)

__global__ void __launch_bounds__(TPB, 2)
decoder_kernel(const float* __restrict__ X,
               const float* __restrict__ H,
               const float* __restrict__ xn,
               const float* __restrict__ W_in,
               const float* __restrict__ b_in,
               const float* __restrict__ W_ih,
               const float* __restrict__ W_hh,
               const float* __restrict__ b_ih,
               const float* __restrict__ b_hh,
               const float* __restrict__ W_out,
               const float* __restrict__ b_out,
               float* __restrict__ out)
{
    extern __shared__ __align__(16) unsigned char smem_raw[];
    ulonglong2* const WRZ = (ulonglong2*)smem_raw;
    ulonglong2* const WN  = WRZ + 64 * 32;
    float4* const GIA = (float4*)(WN + 64 * 16);
    float4* const GIB = GIA + 64;
    float4* const GIC = GIB + 64;
    float*  const F0f = (float*)(GIC + 64);               // 256 floats
    float*  const WO  = F0f + 256;

    const int tid = threadIdx.x;

    // ---- setup phase: pack W_hh, build fused input weights ----
    for (int e = tid; e < 64 * 32; e += TPB) {
        int u = e >> 5, kp = e & 31;
        float a0 = W_hh[u * 64 + 2 * kp];
        float a1 = W_hh[u * 64 + 2 * kp + 1];
        float b0 = W_hh[(64 + u) * 64 + 2 * kp];
        float b1 = W_hh[(64 + u) * 64 + 2 * kp + 1];
        ulonglong2 v; v.x = pack2(a0, a1); v.y = pack2(b0, b1);
        WRZ[e] = v;
    }
    for (int e = tid; e < 64 * 16; e += TPB) {
        int u = e >> 4, kq = e & 15;
        const float* wn = W_hh + (128 + u) * 64 + 4 * kq;
        ulonglong2 v; v.x = pack2(wn[0], wn[1]); v.y = pack2(wn[2], wn[3]);
        WN[e] = v;
    }
    for (int j = tid; j < 192; j += TPB) {
        // F[j][0..3] = W_ih[j] . W_in[:,c] ;  bF = W_ih[j] . b_in + b_ih[j]
        float f0 = 0.f, f1 = 0.f, f2 = 0.f, f3 = 0.f, fb = 0.f;
        const float* wih = W_ih + j * 64;
        #pragma unroll 8
        for (int k = 0; k < 64; k++) {
            float w = wih[k];
            f0 = fmaf(w, W_in[k * 4 + 0], f0);
            f1 = fmaf(w, W_in[k * 4 + 1], f1);
            f2 = fmaf(w, W_in[k * 4 + 2], f2);
            f3 = fmaf(w, W_in[k * 4 + 3], f3);
            fb = fmaf(w, b_in[k], fb);
        }
        fb += b_ih[j];
        int gate = j >> 6, u = j & 63;
        if (gate == 0) {
            GIA[u] = make_float4(f1, f2, f3, fb + b_hh[j]);
            F0f[4 * u + 0] = f0;
        } else if (gate == 1) {
            GIB[u] = make_float4(f1, f2, f3, fb + b_hh[j]);
            F0f[4 * u + 1] = f0;
        } else {
            GIC[u] = make_float4(f1, f2, f3, fb);   // b_hh_n applied on the dn side
            F0f[4 * u + 2] = f0;
            F0f[4 * u + 3] = b_hh[j];
        }
    }
    if (tid < 64) WO[tid] = W_out[tid];
    __syncthreads();

    // ---- per-thread recurrence: two rows per thread ----
    const int r0 = blockIdx.x * ROWS_PB + tid;
    const int r1 = r0 + TPB;
    const int b0i = r0 >> 12, c0 = r0 & (C_ - 1);
    const int b1i = r1 >> 12, c1 = r1 & (C_ - 1);

    ull h2a[32], h2b[32];
    {
        const float* Hrow0 = H + (size_t)r0 * HID;
        const float* Hrow1 = H + (size_t)r1 * HID;
        #pragma unroll
        for (int i = 0; i < 16; i++) {
            float4 v0 = *(const float4*)(Hrow0 + 4 * i);
            float4 v1 = *(const float4*)(Hrow1 + 4 * i);
            h2a[2 * i]     = pack2(v0.x, v0.y);
            h2a[2 * i + 1] = pack2(v0.z, v0.w);
            h2b[2 * i]     = pack2(v1.x, v1.y);
            h2b[2 * i + 1] = pack2(v1.z, v1.w);
            g_hbuf[(4 * i + 0) * NROWS + r0] = v0.x;
            g_hbuf[(4 * i + 1) * NROWS + r0] = v0.y;
            g_hbuf[(4 * i + 2) * NROWS + r0] = v0.z;
            g_hbuf[(4 * i + 3) * NROWS + r0] = v0.w;
            g_hbuf[(4 * i + 0) * NROWS + r1] = v1.x;
            g_hbuf[(4 * i + 1) * NROWS + r1] = v1.y;
            g_hbuf[(4 * i + 2) * NROWS + r1] = v1.z;
            g_hbuf[(4 * i + 3) * NROWS + r1] = v1.w;
        }
    }
    float xprev0 = xn[r0];
    float xprev1 = xn[r1];
    const float bout = b_out[0];
    const float* Xb0 = X + (((size_t)(b0i * (T_HIST + T_FC) + T_HIST)) * C_ + c0) * F_IN + 4;
    const float* Xb1 = X + (((size_t)(b1i * (T_HIST + T_FC) + T_HIST)) * C_ + c1) * F_IN + 4;
    float* outb0 = out + (size_t)b0i * T_FC * C_ + c0;
    float* outb1 = out + (size_t)b1i * T_FC * C_ + c1;

    #pragma unroll 1
    for (int t = 0; t < T_FC; t++) {
        float4 xfa = *(const float4*)(Xb0 + (size_t)t * C_ * F_IN);
        float4 xfb = *(const float4*)(Xb1 + (size_t)t * C_ * F_IN);
        float xacc0 = 0.f, xacc1 = 0.f;

        float* hb0p = g_hbuf + r0;   // walks u*NROWS via += NROWS
        float* hb1p = g_hbuf + r1;

        #pragma unroll 1
        for (int u = 0; u < 64; u++) {
            ull ar0 = 0, az0 = 0, an0 = 0, ar1 = 0, az1 = 0, an1 = 0;
            const ulonglong2* wrz = WRZ + (u << 5);
            const ulonglong2* wn  = WN + (u << 4);
            #pragma unroll
            for (int kq = 0; kq < 16; kq++) {
                ulonglong2 w0  = wrz[2 * kq];
                ulonglong2 w1  = wrz[2 * kq + 1];
                ulonglong2 wnn = wn[kq];
                ull ha0 = h2a[2 * kq], ha1 = h2a[2 * kq + 1];
                ull hb0 = h2b[2 * kq], hb1 = h2b[2 * kq + 1];
                ar0 = fma2(w0.x,  ha0, ar0);   ar1 = fma2(w0.x,  hb0, ar1);
                az0 = fma2(w0.y,  ha0, az0);   az1 = fma2(w0.y,  hb0, az1);
                an0 = fma2(wnn.x, ha0, an0);   an1 = fma2(wnn.x, hb0, an1);
                ar0 = fma2(w1.x,  ha1, ar0);   ar1 = fma2(w1.x,  hb1, ar1);
                az0 = fma2(w1.y,  ha1, az0);   az1 = fma2(w1.y,  hb1, az1);
                an0 = fma2(wnn.y, ha1, an0);   an1 = fma2(wnn.y, hb1, an1);
            }
            float4 ga = GIA[u], gb = GIB[u], gc = GIC[u];
            float4 f0 = ((const float4*)F0f)[u];
            float wou = WO[u];

            // ---- row 0 ----
            {
                float2 fr = unpack2(ar0), fz = unpack2(az0), fn = unpack2(an0);
                float dr = fr.x + fr.y, dz = fz.x + fz.y, dn = fn.x + fn.y;
                float gir = fmaf(ga.x, xfa.y, fmaf(ga.y, xfa.z, fmaf(ga.z, xfa.w, fmaf(f0.x, xprev0, ga.w))));
                float giz = fmaf(gb.x, xfa.y, fmaf(gb.y, xfa.z, fmaf(gb.z, xfa.w, fmaf(f0.y, xprev0, gb.w))));
                float gin = fmaf(gc.x, xfa.y, fmaf(gc.y, xfa.z, fmaf(gc.z, xfa.w, fmaf(f0.z, xprev0, gc.w))));
                float rg = sigm(gir + dr);
                float zg = sigm(giz + dz);
                float ng = tanh_(fmaf(rg, dn + f0.w, gin));
                float hu = *hb0p;
                float hn = ng + zg * (hu - ng);
                *hb0p = hn;
                hb0p += NROWS;
                xacc0 = fmaf(wou, hn, xacc0);
            }
            // ---- row 1 ----
            {
                float2 fr = unpack2(ar1), fz = unpack2(az1), fn = unpack2(an1);
                float dr = fr.x + fr.y, dz = fz.x + fz.y, dn = fn.x + fn.y;
                float gir = fmaf(ga.x, xfb.y, fmaf(ga.y, xfb.z, fmaf(ga.z, xfb.w, fmaf(f0.x, xprev1, ga.w))));
                float giz = fmaf(gb.x, xfb.y, fmaf(gb.y, xfb.z, fmaf(gb.z, xfb.w, fmaf(f0.y, xprev1, gb.w))));
                float gin = fmaf(gc.x, xfb.y, fmaf(gc.y, xfb.z, fmaf(gc.z, xfb.w, fmaf(f0.z, xprev1, gc.w))));
                float rg = sigm(gir + dr);
                float zg = sigm(giz + dz);
                float ng = tanh_(fmaf(rg, dn + f0.w, gin));
                float hu = *hb1p;
                float hn = ng + zg * (hu - ng);
                *hb1p = hn;
                hb1p += NROWS;
                xacc1 = fmaf(wou, hn, xacc1);
            }
        }

        float xo0 = xacc0 + bout;
        float xo1 = xacc1 + bout;
        outb0[(size_t)t * C_] = xo0;
        outb1[(size_t)t * C_] = xo1;
        xprev0 = xo0;
        xprev1 = xo1;

        // refresh register copies of h from scratch (L2-hit, coalesced)
        #pragma unroll
        for (int i = 0; i < 16; i++) {
            float a0 = g_hbuf[(4 * i + 0) * NROWS + r0];
            float a1 = g_hbuf[(4 * i + 1) * NROWS + r0];
            float a2 = g_hbuf[(4 * i + 2) * NROWS + r0];
            float a3 = g_hbuf[(4 * i + 3) * NROWS + r0];
            h2a[2 * i]     = pack2(a0, a1);
            h2a[2 * i + 1] = pack2(a2, a3);
            float e0 = g_hbuf[(4 * i + 0) * NROWS + r1];
            float e1 = g_hbuf[(4 * i + 1) * NROWS + r1];
            float e2 = g_hbuf[(4 * i + 2) * NROWS + r1];
            float e3 = g_hbuf[(4 * i + 3) * NROWS + r1];
            h2b[2 * i]     = pack2(e0, e1);
            h2b[2 * i + 1] = pack2(e2, e3);
        }
    }
}

extern "C" void kernel_launch(void* const* d_in, const int* in_sizes, int n_in,
                              void* d_out, int out_size)
{
    const float* X    = (const float*)d_in[0];
    const float* H    = (const float*)d_in[1];
    const float* xn   = (const float*)d_in[2];
    const float* W_in = (const float*)d_in[3];
    const float* b_in = (const float*)d_in[4];
    const float* W_ih = (const float*)d_in[5];
    const float* W_hh = (const float*)d_in[6];
    const float* b_ih = (const float*)d_in[7];
    const float* b_hh = (const float*)d_in[8];
    const float* W_out= (const float*)d_in[9];
    const float* b_out= (const float*)d_in[10];
    float* out = (float*)d_out;

    cudaFuncSetAttribute(decoder_kernel,
                         cudaFuncAttributeMaxDynamicSharedMemorySize, SMEM_BYTES);
    decoder_kernel<<<NBLK, TPB, SMEM_BYTES>>>(X, H, xn, W_in, b_in, W_ih, W_hh,
                                              b_ih, b_hh, W_out, b_out, out);
}